// round 1
// baseline (speedup 1.0000x reference)
#include <cuda_runtime.h>

// PointOnSurfaceLoss: B=8, M=512, N=8192
// inputs: keypoint [B,3,M] f32, pc [B,3,N] f32, sn [B,3,N] f32
// output: loss [B,M,1,1] f32  (B*M = 4096 floats)

#define BATCH 8
#define MM    512
#define NN    8192
#define TM    16              // keypoints per block
#define LANES 16              // lanes per keypoint
#define NTHREADS (TM * LANES) // 256
#define TN    2048            // pc points per shared tile
#define EPSV  1e-7f

__global__ __launch_bounds__(NTHREADS)
void pos_loss_kernel(const float* __restrict__ keypoint,
                     const float* __restrict__ pc,
                     const float* __restrict__ sn,
                     float* __restrict__ out)
{
    __shared__ float xs[TN];
    __shared__ float ys[TN];
    __shared__ float zs[TN];

    const int b     = blockIdx.x >> 5;   // 32 m-tiles per batch
    const int mtile = blockIdx.x & 31;
    const int tid   = threadIdx.x;
    const int kp    = tid >> 4;          // 0..15
    const int lane  = tid & 15;          // 0..15
    const int m     = mtile * TM + kp;

    const float* kpb = keypoint + (size_t)b * 3 * MM;
    const float kx = kpb[0 * MM + m];
    const float ky = kpb[1 * MM + m];
    const float kz = kpb[2 * MM + m];

    const float* pcb = pc + (size_t)b * 3 * NN;

    float best  = 3.4e38f;
    int   bestn = 0;

    for (int n0 = 0; n0 < NN; n0 += TN) {
        __syncthreads();
        // cooperative tile load: 3 rows of TN floats, float4 vectorized
        const float4* px4 = (const float4*)(pcb + 0 * NN + n0);
        const float4* py4 = (const float4*)(pcb + 1 * NN + n0);
        const float4* pz4 = (const float4*)(pcb + 2 * NN + n0);
        float4* sx4 = (float4*)xs;
        float4* sy4 = (float4*)ys;
        float4* sz4 = (float4*)zs;
        #pragma unroll
        for (int i = tid; i < TN / 4; i += NTHREADS) {
            sx4[i] = px4[i];
            sy4[i] = py4[i];
            sz4[i] = pz4[i];
        }
        __syncthreads();

        #pragma unroll 8
        for (int t = 0; t < TN / LANES; ++t) {
            const int nl = t * LANES + lane;      // consecutive lanes -> consecutive words
            const float dx = kx - xs[nl];
            const float dy = ky - ys[nl];
            const float dz = kz - zs[nl];
            const float d2 = dx * dx + dy * dy + dz * dz;
            if (d2 < best) { best = d2; bestn = n0 + nl; }
        }
    }

    // reduce the 16 lanes of each keypoint (width-16 shfl partitions the warp)
    #pragma unroll
    for (int off = 8; off > 0; off >>= 1) {
        const float od = __shfl_down_sync(0xFFFFFFFFu, best,  off, 16);
        const int   oi = __shfl_down_sync(0xFFFFFFFFu, bestn, off, 16);
        if (od < best || (od == best && oi < bestn)) { best = od; bestn = oi; }
    }

    if (lane == 0) {
        const float px = pcb[0 * NN + bestn];
        const float py = pcb[1 * NN + bestn];
        const float pz = pcb[2 * NN + bestn];
        const float* snb = sn + (size_t)b * 3 * NN;
        const float sx = snb[0 * NN + bestn];
        const float sy = snb[1 * NN + bestn];
        const float sz = snb[2 * NN + bestn];
        const float dx = kx - px;
        const float dy = ky - py;
        const float dz = kz - pz;
        const float nrm = sqrtf(dx * dx + dy * dy + dz * dz);
        const float dot = (sx * dx + sy * dy + sz * dz) / (nrm + EPSV);
        out[b * MM + m] = dot * dot;
    }
}

extern "C" void kernel_launch(void* const* d_in, const int* in_sizes, int n_in,
                              void* d_out, int out_size)
{
    const float* keypoint = (const float*)d_in[0]; // 8*3*512
    const float* pc       = (const float*)d_in[1]; // 8*3*8192
    const float* sn       = (const float*)d_in[2]; // 8*3*8192
    float* out            = (float*)d_out;         // 4096

    dim3 grid(BATCH * (MM / TM));  // 256 blocks
    dim3 block(NTHREADS);          // 256 threads
    pos_loss_kernel<<<grid, block>>>(keypoint, pc, sn, out);
}

// round 4
// speedup vs baseline: 1.0389x; 1.0389x over previous
#include <cuda_runtime.h>
#include <cstdint>

// PointOnSurfaceLoss: B=8, M=512, N=8192
// inputs: keypoint [B,3,M] f32, pc [B,3,N] f32, sn [B,3,N] f32
// output: loss [B,M,1,1] f32  (B*M = 4096 floats)

#define BATCH 8
#define MM    512
#define NN    8192
#define WARPS 8               // keypoints per block (1 warp each)
#define NTHREADS (WARPS * 32)
#define TN    2048            // pc points per shared tile
#define EPSV  1e-7f

union f2u {
    float2   f;
    uint64_t u;
};

__device__ __forceinline__ uint64_t add2(uint64_t a, uint64_t b) {
    uint64_t r;
    asm("add.rn.f32x2 %0, %1, %2;" : "=l"(r) : "l"(a), "l"(b));
    return r;
}
__device__ __forceinline__ uint64_t mul2(uint64_t a, uint64_t b) {
    uint64_t r;
    asm("mul.rn.f32x2 %0, %1, %2;" : "=l"(r) : "l"(a), "l"(b));
    return r;
}
__device__ __forceinline__ uint64_t fma2(uint64_t a, uint64_t b, uint64_t c) {
    uint64_t r;
    asm("fma.rn.f32x2 %0, %1, %2, %3;" : "=l"(r) : "l"(a), "l"(b), "l"(c));
    return r;
}
__device__ __forceinline__ uint64_t pack2(float lo, float hi) {
    uint64_t r;
    asm("mov.b64 %0, {%1, %2};" : "=l"(r) : "f"(lo), "f"(hi));
    return r;
}

__global__ __launch_bounds__(NTHREADS)
void pos_loss_kernel(const float* __restrict__ keypoint,
                     const float* __restrict__ pc,
                     const float* __restrict__ sn,
                     float* __restrict__ out)
{
    __shared__ float xs[TN];
    __shared__ float ys[TN];
    __shared__ float zs[TN];

    const int b    = blockIdx.x >> 6;   // 64 m-tiles per batch
    const int mt   = blockIdx.x & 63;
    const int tid  = threadIdx.x;
    const int wid  = tid >> 5;
    const int lane = tid & 31;
    const int m    = mt * WARPS + wid;  // keypoint handled by this warp

    const float* kpb = keypoint + (size_t)b * 3 * MM;
    const float kx = kpb[0 * MM + m];
    const float ky = kpb[1 * MM + m];
    const float kz = kpb[2 * MM + m];
    const uint64_t nkx2 = pack2(-kx, -kx);
    const uint64_t nky2 = pack2(-ky, -ky);
    const uint64_t nkz2 = pack2(-kz, -kz);

    const float* pcb = pc + (size_t)b * 3 * NN;

    float best  = 3.4e38f;
    int   bcode = 0;           // 2*global_iter + which_of_pair (8+1 bits)

    const float2* xs2 = (const float2*)xs;
    const float2* ys2 = (const float2*)ys;
    const float2* zs2 = (const float2*)zs;

    int tbase = 0;             // global iteration base (each iter = 64 points / warp)
    for (int n0 = 0; n0 < NN; n0 += TN) {
        __syncthreads();
        // cooperative tile load: 3 rows of TN floats, float4 vectorized (L2 hits)
        const float4* px4 = (const float4*)(pcb + 0 * NN + n0);
        const float4* py4 = (const float4*)(pcb + 1 * NN + n0);
        const float4* pz4 = (const float4*)(pcb + 2 * NN + n0);
        float4* sx4 = (float4*)xs;
        float4* sy4 = (float4*)ys;
        float4* sz4 = (float4*)zs;
        #pragma unroll
        for (int i = tid; i < TN / 4; i += NTHREADS) {
            sx4[i] = px4[i];
            sy4[i] = py4[i];
            sz4[i] = pz4[i];
        }
        __syncthreads();

        #pragma unroll 8
        for (int t = 0; t < TN / 64; ++t) {        // each iter: lane takes pair (2*lane, 2*lane+1)
            const int sidx = t * 32 + lane;
            f2u xv, yv, zv;
            xv.f = xs2[sidx];                      // LDS.64, conflict-free
            yv.f = ys2[sidx];
            zv.f = zs2[sidx];
            const uint64_t dx = add2(xv.u, nkx2);  // (p - k), same squared norm
            const uint64_t dy = add2(yv.u, nky2);
            const uint64_t dz = add2(zv.u, nkz2);
            uint64_t d2p = mul2(dx, dx);
            d2p = fma2(dy, dy, d2p);
            d2p = fma2(dz, dz, d2p);
            f2u d2; d2.u = d2p;

            const int cbase = (tbase + t) * 2;
            // tournament within the pair: tie keeps lower index (element 0)
            float dloc; int cloc;
            if (d2.f.y < d2.f.x) { dloc = d2.f.y; cloc = cbase + 1; }
            else                 { dloc = d2.f.x; cloc = cbase;     }
            // vs running best: strict < keeps earlier (lower-n) winner
            if (dloc < best) { best = dloc; bcode = cloc; }
        }
        tbase += TN / 64;
    }

    // reconstruct global point index: n = titer*64 + 2*lane + bit
    int bestn = ((bcode >> 1) << 6) + 2 * lane + (bcode & 1);

    // full-warp argmin reduction with first-occurrence (lowest n) tie-break
    #pragma unroll
    for (int off = 16; off > 0; off >>= 1) {
        const float od = __shfl_down_sync(0xFFFFFFFFu, best,  off);
        const int   on = __shfl_down_sync(0xFFFFFFFFu, bestn, off);
        if (od < best || (od == best && on < bestn)) { best = od; bestn = on; }
    }

    if (lane == 0) {
        const float px = pcb[0 * NN + bestn];
        const float py = pcb[1 * NN + bestn];
        const float pz = pcb[2 * NN + bestn];
        const float* snb = sn + (size_t)b * 3 * NN;
        const float sx = snb[0 * NN + bestn];
        const float sy = snb[1 * NN + bestn];
        const float sz = snb[2 * NN + bestn];
        const float dx = kx - px;
        const float dy = ky - py;
        const float dz = kz - pz;
        const float nrm = sqrtf(dx * dx + dy * dy + dz * dz);
        const float dot = (sx * dx + sy * dy + sz * dz) / (nrm + EPSV);
        out[b * MM + m] = dot * dot;
    }
}

extern "C" void kernel_launch(void* const* d_in, const int* in_sizes, int n_in,
                              void* d_out, int out_size)
{
    const float* keypoint = (const float*)d_in[0]; // 8*3*512
    const float* pc       = (const float*)d_in[1]; // 8*3*8192
    const float* sn       = (const float*)d_in[2]; // 8*3*8192
    float* out            = (float*)d_out;         // 4096

    dim3 grid(BATCH * (MM / WARPS));  // 512 blocks
    dim3 block(NTHREADS);             // 256 threads
    pos_loss_kernel<<<grid, block>>>(keypoint, pc, sn, out);
}

// round 5
// speedup vs baseline: 1.2640x; 1.2166x over previous
#include <cuda_runtime.h>
#include <cstdint>

// PointOnSurfaceLoss: B=8, M=512, N=8192
// inputs: keypoint [B,3,M] f32, pc [B,3,N] f32, sn [B,3,N] f32
// output: loss [B,M,1,1] f32  (B*M = 4096 floats)
//
// Mapping: lane = keypoint (32 keypoints per block), 32 warps split N.
// Point pairs are BROADCAST from shared (all lanes read same address ->
// conflict-free, crossbar cost ~1/64 of the per-lane-point layout).

#define BATCH 8
#define MM    512
#define NN    8192
#define NWARP 32
#define NTHREADS (NWARP * 32)   // 1024
#define TN    2048              // pc points per shared tile
#define NPASS (NN / TN)         // 4
#define EPSV  1e-7f

union f2u {
    float2   f;
    uint64_t u;
};

__device__ __forceinline__ uint64_t add2(uint64_t a, uint64_t b) {
    uint64_t r;
    asm("add.rn.f32x2 %0, %1, %2;" : "=l"(r) : "l"(a), "l"(b));
    return r;
}
__device__ __forceinline__ uint64_t mul2(uint64_t a, uint64_t b) {
    uint64_t r;
    asm("mul.rn.f32x2 %0, %1, %2;" : "=l"(r) : "l"(a), "l"(b));
    return r;
}
__device__ __forceinline__ uint64_t fma2(uint64_t a, uint64_t b, uint64_t c) {
    uint64_t r;
    asm("fma.rn.f32x2 %0, %1, %2, %3;" : "=l"(r) : "l"(a), "l"(b), "l"(c));
    return r;
}
__device__ __forceinline__ uint64_t pack2(float lo, float hi) {
    uint64_t r;
    asm("mov.b64 %0, {%1, %2};" : "=l"(r) : "f"(lo), "f"(hi));
    return r;
}

__global__ __launch_bounds__(NTHREADS)
void pos_loss_kernel(const float* __restrict__ keypoint,
                     const float* __restrict__ pc,
                     const float* __restrict__ sn,
                     float* __restrict__ out)
{
    __shared__ float xs[TN];
    __shared__ float ys[TN];
    __shared__ float zs[TN];
    __shared__ float red_d[NTHREADS];
    __shared__ int   red_i[NTHREADS];

    const int grp  = blockIdx.x;        // 128 groups of 32 keypoints
    const int b    = grp >> 4;          // 16 groups per batch
    const int tid  = threadIdx.x;
    const int wid  = tid >> 5;
    const int lane = tid & 31;
    const int m    = (grp & 15) * 32 + lane;   // this lane's keypoint

    const float* kpb = keypoint + (size_t)b * 3 * MM;
    const float kx = kpb[0 * MM + m];
    const float ky = kpb[1 * MM + m];
    const float kz = kpb[2 * MM + m];
    const uint64_t nkx2 = pack2(-kx, -kx);
    const uint64_t nky2 = pack2(-ky, -ky);
    const uint64_t nkz2 = pack2(-kz, -kz);

    const float* pcb = pc + (size_t)b * 3 * NN;

    float best  = 3.4e38f;
    int   bcode = 0;     // (pass*32 + t)*2 + bit

    const float2* xs2 = (const float2*)xs;
    const float2* ys2 = (const float2*)ys;
    const float2* zs2 = (const float2*)zs;
    const int pbase = wid * 32;   // this warp's pair chunk within each tile

    for (int pass = 0; pass < NPASS; ++pass) {
        __syncthreads();
        // cooperative tile load: 3 rows of TN floats, float4 vectorized (L2 hits)
        const int n0 = pass * TN;
        const float4* px4 = (const float4*)(pcb + 0 * NN + n0);
        const float4* py4 = (const float4*)(pcb + 1 * NN + n0);
        const float4* pz4 = (const float4*)(pcb + 2 * NN + n0);
        float4* sx4 = (float4*)xs;
        float4* sy4 = (float4*)ys;
        float4* sz4 = (float4*)zs;
        if (tid < TN / 4) {          // 512 loaders per row
            sx4[tid] = px4[tid];
            sy4[tid] = py4[tid];
            sz4[tid] = pz4[tid];
        }
        __syncthreads();

        // warp covers pairs [wid*32, wid*32+32) of this tile; every lane
        // evaluates the SAME pair against its own keypoint (broadcast LDS).
        #pragma unroll
        for (int t = 0; t < 32; ++t) {
            const int sidx = pbase + t;
            f2u xv, yv, zv;
            xv.f = xs2[sidx];
            yv.f = ys2[sidx];
            zv.f = zs2[sidx];
            const uint64_t dx = add2(xv.u, nkx2);   // (p - k)
            const uint64_t dy = add2(yv.u, nky2);
            const uint64_t dz = add2(zv.u, nkz2);
            uint64_t d2p = mul2(dx, dx);
            d2p = fma2(dy, dy, d2p);
            d2p = fma2(dz, dz, d2p);
            f2u d2; d2.u = d2p;

            const int cbase = (pass * 32 + t) * 2;
            // within-pair tournament: tie keeps element 0 (lower n)
            float dloc; int cloc;
            if (d2.f.y < d2.f.x) { dloc = d2.f.y; cloc = cbase + 1; }
            else                 { dloc = d2.f.x; cloc = cbase;     }
            // vs running best: strict < keeps earlier (lower-n) winner
            // (for fixed warp, n is ascending in (pass, t))
            if (dloc < best) { best = dloc; bcode = cloc; }
        }
    }

    // decode global point index: n = pass*2048 + wid*64 + 2*t + bit
    {
        const int pairidx = bcode >> 1;
        const int pass    = pairidx >> 5;
        const int t       = pairidx & 31;
        const int n       = pass * TN + wid * 64 + (t << 1) + (bcode & 1);
        red_d[wid * 32 + lane] = best;
        red_i[wid * 32 + lane] = n;
    }
    __syncthreads();

    // warp 0 reduces the 32 warp-partials per keypoint; warps own interleaved
    // n-ranges, so ties MUST break on the index value (first occurrence).
    if (wid == 0) {
        float bd = red_d[lane];
        int   bn = red_i[lane];
        #pragma unroll
        for (int w = 1; w < NWARP; ++w) {
            const float od = red_d[w * 32 + lane];
            const int   on = red_i[w * 32 + lane];
            if (od < bd || (od == bd && on < bn)) { bd = od; bn = on; }
        }

        const float px = pcb[0 * NN + bn];
        const float py = pcb[1 * NN + bn];
        const float pz = pcb[2 * NN + bn];
        const float* snb = sn + (size_t)b * 3 * NN;
        const float sx = snb[0 * NN + bn];
        const float sy = snb[1 * NN + bn];
        const float sz = snb[2 * NN + bn];
        const float dx = kx - px;
        const float dy = ky - py;
        const float dz = kz - pz;
        const float nrm = sqrtf(dx * dx + dy * dy + dz * dz);
        const float dot = (sx * dx + sy * dy + sz * dz) / (nrm + EPSV);
        out[b * MM + m] = dot * dot;
    }
}

extern "C" void kernel_launch(void* const* d_in, const int* in_sizes, int n_in,
                              void* d_out, int out_size)
{
    const float* keypoint = (const float*)d_in[0]; // 8*3*512
    const float* pc       = (const float*)d_in[1]; // 8*3*8192
    const float* sn       = (const float*)d_in[2]; // 8*3*8192
    float* out            = (float*)d_out;         // 4096

    dim3 grid(BATCH * (MM / 32));   // 128 blocks (32 keypoints each)
    dim3 block(NTHREADS);           // 1024 threads = 32 warps
    pos_loss_kernel<<<grid, block>>>(keypoint, pc, sn, out);
}